// round 5
// baseline (speedup 1.0000x reference)
#include <cuda_runtime.h>
#include <math.h>
#include <float.h>

#define NB   50
#define NPG  2000
#define EPG  12000
#define ETOT (NB*EPG)      // 600000
#define N0   (NB*NPG)      // 100000
#define NHID 128
#define KP1  1600
#define KP2  1280
#define KP3  1024

// ---------------- device scratch (load-time allocation, allowed) -------------
__device__ float g_h[(size_t)N0 * NHID];        // GEMM output
__device__ float g_y[(size_t)N0 * NHID];        // post-GCN activations
__device__ float g_xo[(size_t)NB * KP1 * NHID]; // pooled x
__device__ float g_deg[N0];
__device__ float g_dis[N0];
__device__ float g_sp[N0];
__device__ float g_score[N0];
__device__ int   g_src[ETOT];
__device__ int   g_dst[ETOT];
__device__ float g_w[ETOT];
__device__ int   g_map[N0];
__device__ int   g_perm[NB * KP1];
__device__ float g_read[NB * 256];              // accumulated x1+x2+x3

// ---------------- small utility kernels -------------------------------------
__global__ void edge_init_k(const int* __restrict__ ei, int* src, int* dst, float* w, int E) {
    int e = blockIdx.x * blockDim.x + threadIdx.x;
    if (e < E) { src[e] = ei[e]; dst[e] = ei[E + e]; w[e] = 1.0f; }
}

__global__ void zero_k(float* p, int n) {
    int i = blockIdx.x * blockDim.x + threadIdx.x;
    if (i < n) p[i] = 0.0f;
}

__global__ void deg_init_k(float* deg, int N) {
    int i = blockIdx.x * blockDim.x + threadIdx.x;
    if (i < N) deg[i] = 1.0f;
}

__global__ void deg_acc_k(const int* __restrict__ dst, const float* __restrict__ w,
                          float* deg, int E) {
    int e = blockIdx.x * blockDim.x + threadIdx.x;
    if (e < E) {
        float ww = w[e];
        if (ww != 0.0f) atomicAdd(&deg[dst[e]], ww);
    }
}

__global__ void dis_k(const float* __restrict__ deg, float* dis, int N) {
    int i = blockIdx.x * blockDim.x + threadIdx.x;
    if (i < N) dis[i] = rsqrtf(deg[i]);
}

// ---------------- f32x2 helpers ----------------------------------------------
__device__ __forceinline__ void fma2(unsigned long long& d, unsigned long long a,
                                     unsigned long long b) {
    asm("fma.rn.f32x2 %0, %1, %2, %0;" : "+l"(d) : "l"(a), "l"(b));
}
__device__ __forceinline__ float f2lo(unsigned long long v) {
    return __uint_as_float((unsigned)(v & 0xffffffffu));
}
__device__ __forceinline__ float f2hi(unsigned long long v) {
    return __uint_as_float((unsigned)(v >> 32));
}

// ---------------- GEMM: H[N,128] = X[N,K] @ W[K,128]; Y = H/deg + b ----------
// 128x128 tile, 256 threads, 8x8 per thread via f32x2 (FFMA2) accumulators.
__global__ __launch_bounds__(256, 2)
void gemm_k(const float* __restrict__ X, const float* __restrict__ W,
            const float* __restrict__ deg, const float* __restrict__ b,
            float* __restrict__ H, float* __restrict__ Y, int N, int K) {
    __shared__ float2 xs2[16][129];   // duplicated (a,a) pairs; [kk][row]
    __shared__ float  ws[16][128];
    int tid = threadIdx.x;
    int tx = tid & 15;    // cols tx*8 .. +7
    int ty = tid >> 4;    // rows ty*8 .. +7
    int row0 = blockIdx.x * 128;

    unsigned long long acc[8][4];
#pragma unroll
    for (int i = 0; i < 8; i++)
#pragma unroll
        for (int c = 0; c < 4; c++) acc[i][c] = 0ULL;

    int lr  = tid >> 1;        // X-load row 0..127
    int lcg = tid & 1;         // X-load col group (8 floats)

    for (int kb = 0; kb < K; kb += 16) {
        // issue global loads first (latency overlaps barrier)
        float4 v0 = make_float4(0.f, 0.f, 0.f, 0.f), v1 = v0;
        int grow = row0 + lr;
        if (grow < N) {
            const float* xp = X + (size_t)grow * K + kb + lcg * 8;
            v0 = *(const float4*)(xp);
            v1 = *(const float4*)(xp + 4);
        }
        float4 w0 = *(const float4*)(W + (size_t)(kb + ty) * 128 + tx * 8);
        float4 w1 = *(const float4*)(W + (size_t)(kb + ty) * 128 + tx * 8 + 4);
        __syncthreads();
        {
            float xv[8] = {v0.x, v0.y, v0.z, v0.w, v1.x, v1.y, v1.z, v1.w};
#pragma unroll
            for (int j = 0; j < 8; j++)
                xs2[lcg * 8 + j][lr] = make_float2(xv[j], xv[j]);
            *(float4*)&ws[ty][tx * 8]     = w0;
            *(float4*)&ws[ty][tx * 8 + 4] = w1;
        }
        __syncthreads();
#pragma unroll
        for (int kk = 0; kk < 16; kk++) {
            unsigned long long a[8];
#pragma unroll
            for (int i = 0; i < 8; i++)
                a[i] = *(const unsigned long long*)&xs2[kk][ty * 8 + i];
            const unsigned long long* wp = (const unsigned long long*)&ws[kk][tx * 8];
            unsigned long long wv0 = wp[0], wv1 = wp[1], wv2 = wp[2], wv3 = wp[3];
#pragma unroll
            for (int i = 0; i < 8; i++) {
                fma2(acc[i][0], a[i], wv0);
                fma2(acc[i][1], a[i], wv1);
                fma2(acc[i][2], a[i], wv2);
                fma2(acc[i][3], a[i], wv3);
            }
        }
    }

    float4 b0 = *(const float4*)(b + tx * 8);
    float4 b1 = *(const float4*)(b + tx * 8 + 4);
#pragma unroll
    for (int i = 0; i < 8; i++) {
        int grow = row0 + ty * 8 + i;
        if (grow < N) {
            float4 h0, h1;
            h0.x = f2lo(acc[i][0]); h0.y = f2hi(acc[i][0]);
            h0.z = f2lo(acc[i][1]); h0.w = f2hi(acc[i][1]);
            h1.x = f2lo(acc[i][2]); h1.y = f2hi(acc[i][2]);
            h1.z = f2lo(acc[i][3]); h1.w = f2hi(acc[i][3]);
            float* hp = H + (size_t)grow * 128 + tx * 8;
            *(float4*)(hp)     = h0;
            *(float4*)(hp + 4) = h1;
            float inv = 1.0f / deg[grow];
            float4 y0, y1;
            y0.x = h0.x * inv + b0.x; y0.y = h0.y * inv + b0.y;
            y0.z = h0.z * inv + b0.z; y0.w = h0.w * inv + b0.w;
            y1.x = h1.x * inv + b1.x; y1.y = h1.y * inv + b1.y;
            y1.z = h1.z * inv + b1.z; y1.w = h1.w * inv + b1.w;
            float* yp = Y + (size_t)grow * 128 + tx * 8;
            *(float4*)(yp)     = y0;
            *(float4*)(yp + 4) = y1;
        }
    }
}

// edge aggregation: y[dst] += h[src] * norm ; warp per edge, red.v4
__global__ void agg_k(const int* __restrict__ src, const int* __restrict__ dst,
                      const float* __restrict__ w, const float* __restrict__ dis,
                      const float* __restrict__ h, float* __restrict__ y, int E) {
    int e = blockIdx.x * 8 + (threadIdx.x >> 5);
    int lane = threadIdx.x & 31;
    if (e < E) {
        float ww = w[e];
        if (ww != 0.0f) {
            int s = src[e], d = dst[e];
            float norm = ww * dis[s] * dis[d];
            float4 v = ((const float4*)(h + (size_t)s * 128))[lane];
            float* yp = y + (size_t)d * 128 + lane * 4;
            float a0 = v.x * norm, a1 = v.y * norm, a2 = v.z * norm, a3 = v.w * norm;
            asm volatile("red.global.add.v4.f32 [%0], {%1, %2, %3, %4};"
                         :: "l"(yp), "f"(a0), "f"(a1), "f"(a2), "f"(a3) : "memory");
        }
    }
}

// relu(y) in-place + sp = y.Ws + score = sp/deg + bs ; warp per node
__global__ void relu_score_k(float* __restrict__ y, const float* __restrict__ Ws,
                             const float* __restrict__ deg, const float* __restrict__ bs,
                             float* __restrict__ sp, float* __restrict__ score, int N) {
    int i = blockIdx.x * 8 + (threadIdx.x >> 5);
    int lane = threadIdx.x & 31;
    if (i < N) {
        float4* yp = (float4*)(y + (size_t)i * 128) + lane;
        float4 a = *yp;
        a.x = fmaxf(a.x, 0.f); a.y = fmaxf(a.y, 0.f);
        a.z = fmaxf(a.z, 0.f); a.w = fmaxf(a.w, 0.f);
        *yp = a;
        float4 wv = ((const float4*)Ws)[lane];
        float s = a.x * wv.x + a.y * wv.y + a.z * wv.z + a.w * wv.w;
#pragma unroll
        for (int off = 16; off > 0; off >>= 1) s += __shfl_down_sync(0xffffffffu, s, off);
        if (lane == 0) {
            sp[i] = s;
            score[i] = s / deg[i] + bs[0];
        }
    }
}

__global__ void score_agg_k(const int* __restrict__ src, const int* __restrict__ dst,
                            const float* __restrict__ w, const float* __restrict__ dis,
                            const float* __restrict__ sp, float* score, int E) {
    int e = blockIdx.x * blockDim.x + threadIdx.x;
    if (e < E) {
        float ww = w[e];
        if (ww != 0.0f) {
            int s = src[e], d = dst[e];
            atomicAdd(&score[d], sp[s] * ww * dis[s] * dis[d]);
        }
    }
}

// ---------------- top-k per graph (bitonic sort of 2048 packed keys) --------
__global__ void topk_k(const float* __restrict__ score, int* __restrict__ map,
                       int* __restrict__ perm, int n, int k) {
    __shared__ unsigned long long keys[2048];
    int g = blockIdx.x;
    unsigned t = threadIdx.x;  // 1024 threads
    for (int p = t; p < 2048; p += 1024) {
        unsigned long long key;
        if (p < n) {
            unsigned u = __float_as_uint(score[g * n + p]);
            u = (u & 0x80000000u) ? ~u : (u | 0x80000000u);
            key = ((unsigned long long)(~u) << 32) | (unsigned)p;
        } else {
            key = ~0ULL;
        }
        keys[p] = key;
    }
    __syncthreads();
    for (unsigned size = 2; size < 2048; size <<= 1) {
        unsigned ddd = (t & (size >> 1)) != 0;
        for (unsigned stride = size >> 1; stride > 0; stride >>= 1) {
            __syncthreads();
            unsigned pos = 2 * t - (t & (stride - 1));
            unsigned long long a = keys[pos], bbv = keys[pos + stride];
            if ((a > bbv) != ddd) { keys[pos] = bbv; keys[pos + stride] = a; }
        }
    }
    for (unsigned stride = 1024; stride > 0; stride >>= 1) {
        __syncthreads();
        unsigned pos = 2 * t - (t & (stride - 1));
        unsigned long long a = keys[pos], bbv = keys[pos + stride];
        if (a > bbv) { keys[pos] = bbv; keys[pos + stride] = a; }
    }
    __syncthreads();
    for (int p = t; p < 2048; p += 1024) {
        unsigned idxv = (unsigned)(keys[p] & 0xFFFFFFFFu);
        if (idxv < (unsigned)n) {
            if (p < k) {
                map[g * n + (int)idxv] = g * k + p;
                perm[g * k + p] = g * n + (int)idxv;
            } else {
                map[g * n + (int)idxv] = -1;
            }
        }
    }
}

// gather + tanh gate fused
__global__ void gather_k(const float* __restrict__ y, const int* __restrict__ perm,
                         const float* __restrict__ score, float* __restrict__ xo, int Nout) {
    int idx = blockIdx.x * blockDim.x + threadIdx.x;
    if (idx < Nout * 32) {
        int m = idx >> 5;
        int q = idx & 31;
        int pm = perm[m];
        float tv = tanhf(score[pm]);
        float4 v = ((const float4*)(y + (size_t)pm * 128))[q];
        v.x *= tv; v.y *= tv; v.z *= tv; v.w *= tv;
        ((float4*)xo)[idx] = v;
    }
}

// readout: accumulate [max || mean] per graph into readb (+=)
__global__ void readout_k(const float* __restrict__ xo, int k, float* __restrict__ readb) {
    __shared__ float smx[8][128];
    __shared__ float ssm[8][128];
    int g = blockIdx.x;
    int f = threadIdx.x & 127;
    int ty = threadIdx.x >> 7;  // 0..7
    float mx = -FLT_MAX, sm = 0.0f;
    for (int i = ty; i < k; i += 8) {
        float v = xo[((size_t)(g * k + i)) * 128 + f];
        mx = fmaxf(mx, v);
        sm += v;
    }
    smx[ty][f] = mx;
    ssm[ty][f] = sm;
    __syncthreads();
    if (ty == 0) {
#pragma unroll
        for (int j = 1; j < 8; j++) { mx = fmaxf(mx, smx[j][f]); sm += ssm[j][f]; }
        readb[g * 256 + f]       += mx;
        readb[g * 256 + 128 + f] += sm / (float)k;
    }
}

__global__ void remap_k(const int* __restrict__ map, int* src, int* dst, float* w, int E) {
    int e = blockIdx.x * blockDim.x + threadIdx.x;
    if (e < E) {
        float ww = w[e];
        int ns = map[src[e]];
        int nd = map[dst[e]];
        bool valid = (ns >= 0) && (nd >= 0) && (ww > 0.0f);
        src[e] = valid ? ns : 0;
        dst[e] = valid ? nd : 0;
        w[e]   = valid ? ww : 0.0f;
    }
}

// out[g,j] = relu(sum_c readb[g,c]*Wl[c,j] + bl[j])
__global__ void final_k(const float* __restrict__ readb, const float* __restrict__ Wl,
                        const float* __restrict__ bl, float* __restrict__ out) {
    __shared__ float row[256];
    int g = blockIdx.x, j = threadIdx.x;  // 128 threads
    row[j]       = readb[g * 256 + j];
    row[128 + j] = readb[g * 256 + 128 + j];
    __syncthreads();
    float acc = bl[j];
#pragma unroll 8
    for (int c = 0; c < 256; c++) acc += row[c] * Wl[c * 128 + j];
    out[g * 128 + j] = fmaxf(acc, 0.0f);
}

// ---------------- host driver -----------------------------------------------
static void run_stage(const float* x_in, int Fin, int N, int n, int k,
                      const float* W, const float* b, const float* Ws, const float* bs,
                      float* h, float* y, float* xo,
                      float* deg, float* dis, float* sp, float* score,
                      int* src, int* dst, float* w, int* map, int* perm,
                      float* readb, bool do_remap) {
    int Nout = NB * k;
    deg_init_k<<<(N + 255) / 256, 256>>>(deg, N);
    deg_acc_k<<<(ETOT + 255) / 256, 256>>>(dst, w, deg, ETOT);
    dis_k<<<(N + 255) / 256, 256>>>(deg, dis, N);
    gemm_k<<<(N + 127) / 128, 256>>>(x_in, W, deg, b, h, y, N, Fin);
    agg_k<<<(ETOT + 7) / 8, 256>>>(src, dst, w, dis, h, y, ETOT);
    relu_score_k<<<(N + 7) / 8, 256>>>(y, Ws, deg, bs, sp, score, N);
    score_agg_k<<<(ETOT + 255) / 256, 256>>>(src, dst, w, dis, sp, score, ETOT);
    topk_k<<<NB, 1024>>>(score, map, perm, n, k);
    gather_k<<<(Nout * 32 + 255) / 256, 256>>>(y, perm, score, xo, Nout);
    readout_k<<<NB, 1024>>>(xo, k, readb);
    if (do_remap)
        remap_k<<<(ETOT + 255) / 256, 256>>>(map, src, dst, w, ETOT);
}

extern "C" void kernel_launch(void* const* d_in, const int* in_sizes, int n_in,
                              void* d_out, int out_size) {
    const float* x   = (const float*)d_in[0];
    const float* W1  = (const float*)d_in[1];
    const float* b1  = (const float*)d_in[2];
    const float* Ws1 = (const float*)d_in[3];
    const float* bs1 = (const float*)d_in[4];
    const float* W2  = (const float*)d_in[5];
    const float* b2  = (const float*)d_in[6];
    const float* Ws2 = (const float*)d_in[7];
    const float* bs2 = (const float*)d_in[8];
    const float* W3  = (const float*)d_in[9];
    const float* b3  = (const float*)d_in[10];
    const float* Ws3 = (const float*)d_in[11];
    const float* bs3 = (const float*)d_in[12];
    const float* Wl  = (const float*)d_in[13];
    const float* bl  = (const float*)d_in[14];
    const int*   ei  = (const int*)d_in[15];
    float* out = (float*)d_out;

    float *h, *y, *xo, *deg, *dis, *sp, *score, *w, *readb;
    int *src, *dst, *map, *perm;
    cudaGetSymbolAddress((void**)&h, g_h);
    cudaGetSymbolAddress((void**)&y, g_y);
    cudaGetSymbolAddress((void**)&xo, g_xo);
    cudaGetSymbolAddress((void**)&deg, g_deg);
    cudaGetSymbolAddress((void**)&dis, g_dis);
    cudaGetSymbolAddress((void**)&sp, g_sp);
    cudaGetSymbolAddress((void**)&score, g_score);
    cudaGetSymbolAddress((void**)&src, g_src);
    cudaGetSymbolAddress((void**)&dst, g_dst);
    cudaGetSymbolAddress((void**)&w, g_w);
    cudaGetSymbolAddress((void**)&map, g_map);
    cudaGetSymbolAddress((void**)&perm, g_perm);
    cudaGetSymbolAddress((void**)&readb, g_read);

    edge_init_k<<<(ETOT + 255) / 256, 256>>>(ei, src, dst, w, ETOT);
    zero_k<<<(NB * 256 + 255) / 256, 256>>>(readb, NB * 256);

    run_stage(x, 256, N0, NPG, KP1, W1, b1, Ws1, bs1,
              h, y, xo, deg, dis, sp, score, src, dst, w, map, perm, readb, true);
    run_stage(xo, 128, NB * KP1, KP1, KP2, W2, b2, Ws2, bs2,
              h, y, xo, deg, dis, sp, score, src, dst, w, map, perm, readb, true);
    run_stage(xo, 128, NB * KP2, KP2, KP3, W3, b3, Ws3, bs3,
              h, y, xo, deg, dis, sp, score, src, dst, w, map, perm, readb, false);
    final_k<<<NB, 128>>>(readb, Wl, bl, out);
}

// round 9
// speedup vs baseline: 1.6623x; 1.6623x over previous
#include <cuda_runtime.h>
#include <math.h>
#include <float.h>

#define NB   50
#define NPG  2000
#define EPG  12000
#define ETOT (NB*EPG)      // 600000
#define N0   (NB*NPG)      // 100000
#define NHID 128
#define KP1  1600
#define KP2  1280
#define KP3  1024

// ---------------- device scratch (load-time allocation, allowed) -------------
__device__ float g_h[(size_t)N0 * NHID];        // GEMM output
__device__ float g_y[(size_t)N0 * NHID];        // post-GCN activations
__device__ float g_xo[(size_t)NB * KP1 * NHID]; // pooled x
__device__ float g_dis[N0];
__device__ float g_sp[N0];
__device__ float g_score[N0];
__device__ int   g_src[ETOT];
__device__ int   g_dst[ETOT];
__device__ float g_w[ETOT];
__device__ int   g_map[N0];
__device__ int   g_perm[NB * KP1];
__device__ float g_read[NB * 256];              // accumulated x1+x2+x3
// CSR scratch
__device__ int   g_cnt[N0];
__device__ int   g_rs[N0 + 1];
__device__ int   g_cur[N0];
__device__ int   g_elist[ETOT];
__device__ int   g_bsum[1025];

// ---------------- misc -------------------------------------------------------
__global__ void edge_init_k(const int* __restrict__ ei, int* src, int* dst, float* w, int E) {
    int e = blockIdx.x * blockDim.x + threadIdx.x;
    if (e < E) { src[e] = ei[e]; dst[e] = ei[E + e]; w[e] = 1.0f; }
}

__global__ void zero_f_k(float* p, int n) {
    int i = blockIdx.x * blockDim.x + threadIdx.x;
    if (i < n) p[i] = 0.0f;
}

__global__ void zero_i_k(int* p, int n) {
    int i = blockIdx.x * blockDim.x + threadIdx.x;
    if (i < n) p[i] = 0;
}

// ---------------- CSR build --------------------------------------------------
__global__ void count_k(const int* __restrict__ dst, const float* __restrict__ w,
                        int* __restrict__ cnt, int E) {
    int e = blockIdx.x * blockDim.x + threadIdx.x;
    if (e < E && w[e] != 0.0f) atomicAdd(&cnt[dst[e]], 1);
}

// per-1024-block inclusive scan -> exclusive result + block totals
__global__ void scan1_k(const int* __restrict__ cnt, int* __restrict__ excl,
                        int* __restrict__ bsum, int N) {
    __shared__ int s[1024];
    int tid = threadIdx.x;
    int i = blockIdx.x * 1024 + tid;
    int v = (i < N) ? cnt[i] : 0;
    s[tid] = v;
    __syncthreads();
#pragma unroll
    for (int off = 1; off < 1024; off <<= 1) {
        int t = (tid >= off) ? s[tid - off] : 0;
        __syncthreads();
        s[tid] += t;
        __syncthreads();
    }
    if (i < N) excl[i] = s[tid] - v;
    if (tid == 1023) bsum[blockIdx.x] = s[1023];
}

// scan the (<=1024) block sums; bsum becomes exclusive, bsum[nblk] = total
__global__ void scan2_k(int* __restrict__ bsum, int nblk) {
    __shared__ int s[1024];
    int tid = threadIdx.x;
    int v = (tid < nblk) ? bsum[tid] : 0;
    s[tid] = v;
    __syncthreads();
#pragma unroll
    for (int off = 1; off < 1024; off <<= 1) {
        int t = (tid >= off) ? s[tid - off] : 0;
        __syncthreads();
        s[tid] += t;
        __syncthreads();
    }
    if (tid < nblk) bsum[tid] = s[tid] - v;
    if (tid == nblk - 1) bsum[nblk] = s[tid];
}

// finalize: row_start, cursor, dis = rsqrt(deg)
__global__ void scan3_k(const int* __restrict__ excl, const int* __restrict__ bsum,
                        const int* __restrict__ cnt, int* __restrict__ rs,
                        int* __restrict__ cur, float* __restrict__ dis,
                        int N, int nblk) {
    int i = blockIdx.x * blockDim.x + threadIdx.x;
    if (i < N) {
        int r = excl[i] + bsum[i >> 10];
        rs[i] = r;
        cur[i] = r;
        dis[i] = rsqrtf((float)(cnt[i] + 1));
    } else if (i == N) {
        rs[N] = bsum[nblk];
    }
}

__global__ void fill_k(const int* __restrict__ src, const int* __restrict__ dst,
                       const float* __restrict__ w, int* __restrict__ cur,
                       int* __restrict__ elist, int E) {
    int e = blockIdx.x * blockDim.x + threadIdx.x;
    if (e < E && w[e] != 0.0f) {
        int pos = atomicAdd(&cur[dst[e]], 1);
        elist[pos] = src[e];
    }
}

// ---------------- GEMM: H[N,128] = X[N,K] @ W[K,128]  (R2-proven version) ----
__global__ void gemm_k(const float* __restrict__ X, const float* __restrict__ W,
                       float* __restrict__ H, int N, int K) {
    __shared__ float xs[64][16];
    __shared__ float ws[16][128];
    int tid  = threadIdx.x;
    int row0 = blockIdx.x * 64;
    int tx = tid & 15;   // col group: cols tx*8 .. tx*8+7
    int ty = tid >> 4;   // row group: rows ty*4 .. ty*4+3
    float acc[4][8];
#pragma unroll
    for (int r = 0; r < 4; r++)
#pragma unroll
        for (int c = 0; c < 8; c++) acc[r][c] = 0.0f;

    for (int kb = 0; kb < K; kb += 16) {
        {
            int r = tid >> 2;
            int c = (tid & 3) * 4;
            int grow = row0 + r;
            float4 v = make_float4(0.f, 0.f, 0.f, 0.f);
            if (grow < N) v = *(const float4*)(X + (size_t)grow * K + kb + c);
            *(float4*)&xs[r][c] = v;
        }
        {
            int r = tid >> 4;
            int c = (tid & 15) * 8;
            *(float4*)&ws[r][c]     = *(const float4*)(W + (size_t)(kb + r) * 128 + c);
            *(float4*)&ws[r][c + 4] = *(const float4*)(W + (size_t)(kb + r) * 128 + c + 4);
        }
        __syncthreads();
#pragma unroll
        for (int kk = 0; kk < 16; kk++) {
            float xr[4];
#pragma unroll
            for (int r = 0; r < 4; r++) xr[r] = xs[ty * 4 + r][kk];
            float4 w0 = *(float4*)&ws[kk][tx * 8];
            float4 w1 = *(float4*)&ws[kk][tx * 8 + 4];
            float wr[8] = {w0.x, w0.y, w0.z, w0.w, w1.x, w1.y, w1.z, w1.w};
#pragma unroll
            for (int r = 0; r < 4; r++)
#pragma unroll
                for (int c = 0; c < 8; c++) acc[r][c] += xr[r] * wr[c];
        }
        __syncthreads();
    }
#pragma unroll
    for (int r = 0; r < 4; r++) {
        int grow = row0 + ty * 4 + r;
        if (grow < N) {
            float* dstp = H + (size_t)grow * 128 + tx * 8;
            *(float4*)(dstp)     = make_float4(acc[r][0], acc[r][1], acc[r][2], acc[r][3]);
            *(float4*)(dstp + 4) = make_float4(acc[r][4], acc[r][5], acc[r][6], acc[r][7]);
        }
    }
}

// ---------------- fused CSR aggregation + self-loop + bias + relu + score dot
// warp per destination node
__global__ void agg_fused_k(const int* __restrict__ rs, const int* __restrict__ elist,
                            const float* __restrict__ dis, const float* __restrict__ h,
                            const float* __restrict__ b, const float* __restrict__ Ws,
                            float* __restrict__ y, float* __restrict__ sp, int N) {
    int i = blockIdx.x * 8 + (threadIdx.x >> 5);
    int lane = threadIdx.x & 31;
    if (i >= N) return;
    int e0 = rs[i], e1 = rs[i + 1];
    float4 acc = make_float4(0.f, 0.f, 0.f, 0.f);
    for (int e = e0; e < e1; e++) {
        int s = elist[e];
        float ns = dis[s];
        float4 v = ((const float4*)(h + (size_t)s * 128))[lane];
        acc.x += v.x * ns; acc.y += v.y * ns;
        acc.z += v.z * ns; acc.w += v.w * ns;
    }
    float di = dis[i];
    float invdeg = 1.0f / (float)(e1 - e0 + 1);
    float4 hv = ((const float4*)(h + (size_t)i * 128))[lane];
    float4 bv = ((const float4*)b)[lane];
    float4 yv;
    yv.x = fmaxf(acc.x * di + hv.x * invdeg + bv.x, 0.f);
    yv.y = fmaxf(acc.y * di + hv.y * invdeg + bv.y, 0.f);
    yv.z = fmaxf(acc.z * di + hv.z * invdeg + bv.z, 0.f);
    yv.w = fmaxf(acc.w * di + hv.w * invdeg + bv.w, 0.f);
    ((float4*)(y + (size_t)i * 128))[lane] = yv;
    // score dot: sp[i] = y[i,:] . Ws
    float4 wv = ((const float4*)Ws)[lane];
    float s = yv.x * wv.x + yv.y * wv.y + yv.z * wv.z + yv.w * wv.w;
#pragma unroll
    for (int off = 16; off > 0; off >>= 1) s += __shfl_down_sync(0xffffffffu, s, off);
    if (lane == 0) sp[i] = s;
}

// score[i] = (sum_in sp[src]*dis[src])*dis[i] + sp[i]/deg[i] + bs
__global__ void score_csr_k(const int* __restrict__ rs, const int* __restrict__ elist,
                            const float* __restrict__ dis, const float* __restrict__ sp,
                            const float* __restrict__ bs, float* __restrict__ score, int N) {
    int i = blockIdx.x * blockDim.x + threadIdx.x;
    if (i >= N) return;
    int e0 = rs[i], e1 = rs[i + 1];
    float acc = 0.0f;
    for (int e = e0; e < e1; e++) {
        int s = elist[e];
        acc += sp[s] * dis[s];
    }
    float invdeg = 1.0f / (float)(e1 - e0 + 1);
    score[i] = acc * dis[i] + sp[i] * invdeg + bs[0];
}

// ---------------- top-k per graph (bitonic sort of 2048 packed keys) --------
__global__ void topk_k(const float* __restrict__ score, int* __restrict__ map,
                       int* __restrict__ perm, int n, int k) {
    __shared__ unsigned long long keys[2048];
    int g = blockIdx.x;
    unsigned t = threadIdx.x;  // 1024 threads
    for (int p = t; p < 2048; p += 1024) {
        unsigned long long key;
        if (p < n) {
            unsigned u = __float_as_uint(score[g * n + p]);
            u = (u & 0x80000000u) ? ~u : (u | 0x80000000u);
            key = ((unsigned long long)(~u) << 32) | (unsigned)p;
        } else {
            key = ~0ULL;
        }
        keys[p] = key;
    }
    __syncthreads();
    for (unsigned size = 2; size < 2048; size <<= 1) {
        unsigned ddd = (t & (size >> 1)) != 0;
        for (unsigned stride = size >> 1; stride > 0; stride >>= 1) {
            __syncthreads();
            unsigned pos = 2 * t - (t & (stride - 1));
            unsigned long long a = keys[pos], bbv = keys[pos + stride];
            if ((a > bbv) != ddd) { keys[pos] = bbv; keys[pos + stride] = a; }
        }
    }
    for (unsigned stride = 1024; stride > 0; stride >>= 1) {
        __syncthreads();
        unsigned pos = 2 * t - (t & (stride - 1));
        unsigned long long a = keys[pos], bbv = keys[pos + stride];
        if (a > bbv) { keys[pos] = bbv; keys[pos + stride] = a; }
    }
    __syncthreads();
    for (int p = t; p < 2048; p += 1024) {
        unsigned idxv = (unsigned)(keys[p] & 0xFFFFFFFFu);
        if (idxv < (unsigned)n) {
            if (p < k) {
                map[g * n + (int)idxv] = g * k + p;
                perm[g * k + p] = g * n + (int)idxv;
            } else {
                map[g * n + (int)idxv] = -1;
            }
        }
    }
}

// gather + tanh gate fused
__global__ void gather_k(const float* __restrict__ y, const int* __restrict__ perm,
                         const float* __restrict__ score, float* __restrict__ xo, int Nout) {
    int idx = blockIdx.x * blockDim.x + threadIdx.x;
    if (idx < Nout * 32) {
        int m = idx >> 5;
        int q = idx & 31;
        int pm = perm[m];
        float tv = tanhf(score[pm]);
        float4 v = ((const float4*)(y + (size_t)pm * 128))[q];
        v.x *= tv; v.y *= tv; v.z *= tv; v.w *= tv;
        ((float4*)xo)[idx] = v;
    }
}

// readout: accumulate [max || mean] per graph into readb (+=)
__global__ void readout_k(const float* __restrict__ xo, int k, float* __restrict__ readb) {
    __shared__ float smx[8][128];
    __shared__ float ssm[8][128];
    int g = blockIdx.x;
    int f = threadIdx.x & 127;
    int ty = threadIdx.x >> 7;  // 0..7
    float mx = -FLT_MAX, sm = 0.0f;
    for (int i = ty; i < k; i += 8) {
        float v = xo[((size_t)(g * k + i)) * 128 + f];
        mx = fmaxf(mx, v);
        sm += v;
    }
    smx[ty][f] = mx;
    ssm[ty][f] = sm;
    __syncthreads();
    if (ty == 0) {
#pragma unroll
        for (int j = 1; j < 8; j++) { mx = fmaxf(mx, smx[j][f]); sm += ssm[j][f]; }
        readb[g * 256 + f]       += mx;
        readb[g * 256 + 128 + f] += sm / (float)k;
    }
}

__global__ void remap_k(const int* __restrict__ map, int* src, int* dst, float* w, int E) {
    int e = blockIdx.x * blockDim.x + threadIdx.x;
    if (e < E) {
        float ww = w[e];
        int ns = map[src[e]];
        int nd = map[dst[e]];
        bool valid = (ns >= 0) && (nd >= 0) && (ww > 0.0f);
        src[e] = valid ? ns : 0;
        dst[e] = valid ? nd : 0;
        w[e]   = valid ? ww : 0.0f;
    }
}

// out[g,j] = relu(sum_c readb[g,c]*Wl[c,j] + bl[j])
__global__ void final_k(const float* __restrict__ readb, const float* __restrict__ Wl,
                        const float* __restrict__ bl, float* __restrict__ out) {
    __shared__ float row[256];
    int g = blockIdx.x, j = threadIdx.x;  // 128 threads
    row[j]       = readb[g * 256 + j];
    row[128 + j] = readb[g * 256 + 128 + j];
    __syncthreads();
    float acc = bl[j];
#pragma unroll 8
    for (int c = 0; c < 256; c++) acc += row[c] * Wl[c * 128 + j];
    out[g * 128 + j] = fmaxf(acc, 0.0f);
}

// ---------------- host driver -----------------------------------------------
static void run_stage(const float* x_in, int Fin, int N, int n, int k,
                      const float* W, const float* b, const float* Ws, const float* bs,
                      float* h, float* y, float* xo,
                      float* dis, float* sp, float* score,
                      int* src, int* dst, float* w, int* map, int* perm,
                      int* cnt, int* rs, int* cur, int* elist, int* bsum,
                      float* readb, bool do_remap) {
    int Nout = NB * k;
    int nblk = (N + 1023) / 1024;
    // CSR build
    zero_i_k<<<(N + 255) / 256, 256>>>(cnt, N);
    count_k<<<(ETOT + 255) / 256, 256>>>(dst, w, cnt, ETOT);
    scan1_k<<<nblk, 1024>>>(cnt, cur /*excl scratch*/, bsum, N);
    scan2_k<<<1, 1024>>>(bsum, nblk);
    scan3_k<<<(N + 256) / 256, 256>>>(cur, bsum, cnt, rs, cnt /*reuse cnt as cursor*/, dis, N, nblk);
    fill_k<<<(ETOT + 255) / 256, 256>>>(src, dst, w, cnt, elist, ETOT);
    // dense
    gemm_k<<<(N + 63) / 64, 256>>>(x_in, W, h, N, Fin);
    agg_fused_k<<<(N + 7) / 8, 256>>>(rs, elist, dis, h, b, Ws, y, sp, N);
    score_csr_k<<<(N + 255) / 256, 256>>>(rs, elist, dis, sp, bs, score, N);
    topk_k<<<NB, 1024>>>(score, map, perm, n, k);
    gather_k<<<(Nout * 32 + 255) / 256, 256>>>(y, perm, score, xo, Nout);
    readout_k<<<NB, 1024>>>(xo, k, readb);
    if (do_remap)
        remap_k<<<(ETOT + 255) / 256, 256>>>(map, src, dst, w, ETOT);
}

extern "C" void kernel_launch(void* const* d_in, const int* in_sizes, int n_in,
                              void* d_out, int out_size) {
    const float* x   = (const float*)d_in[0];
    const float* W1  = (const float*)d_in[1];
    const float* b1  = (const float*)d_in[2];
    const float* Ws1 = (const float*)d_in[3];
    const float* bs1 = (const float*)d_in[4];
    const float* W2  = (const float*)d_in[5];
    const float* b2  = (const float*)d_in[6];
    const float* Ws2 = (const float*)d_in[7];
    const float* bs2 = (const float*)d_in[8];
    const float* W3  = (const float*)d_in[9];
    const float* b3  = (const float*)d_in[10];
    const float* Ws3 = (const float*)d_in[11];
    const float* bs3 = (const float*)d_in[12];
    const float* Wl  = (const float*)d_in[13];
    const float* bl  = (const float*)d_in[14];
    const int*   ei  = (const int*)d_in[15];
    float* out = (float*)d_out;

    float *h, *y, *xo, *dis, *sp, *score, *w, *readb;
    int *src, *dst, *map, *perm, *cnt, *rs, *cur, *elist, *bsum;
    cudaGetSymbolAddress((void**)&h, g_h);
    cudaGetSymbolAddress((void**)&y, g_y);
    cudaGetSymbolAddress((void**)&xo, g_xo);
    cudaGetSymbolAddress((void**)&dis, g_dis);
    cudaGetSymbolAddress((void**)&sp, g_sp);
    cudaGetSymbolAddress((void**)&score, g_score);
    cudaGetSymbolAddress((void**)&src, g_src);
    cudaGetSymbolAddress((void**)&dst, g_dst);
    cudaGetSymbolAddress((void**)&w, g_w);
    cudaGetSymbolAddress((void**)&map, g_map);
    cudaGetSymbolAddress((void**)&perm, g_perm);
    cudaGetSymbolAddress((void**)&readb, g_read);
    cudaGetSymbolAddress((void**)&cnt, g_cnt);
    cudaGetSymbolAddress((void**)&rs, g_rs);
    cudaGetSymbolAddress((void**)&cur, g_cur);
    cudaGetSymbolAddress((void**)&elist, g_elist);
    cudaGetSymbolAddress((void**)&bsum, g_bsum);

    edge_init_k<<<(ETOT + 255) / 256, 256>>>(ei, src, dst, w, ETOT);
    zero_f_k<<<(NB * 256 + 255) / 256, 256>>>(readb, NB * 256);

    run_stage(x, 256, N0, NPG, KP1, W1, b1, Ws1, bs1,
              h, y, xo, dis, sp, score, src, dst, w, map, perm,
              cnt, rs, cur, elist, bsum, readb, true);
    run_stage(xo, 128, NB * KP1, KP1, KP2, W2, b2, Ws2, bs2,
              h, y, xo, dis, sp, score, src, dst, w, map, perm,
              cnt, rs, cur, elist, bsum, readb, true);
    run_stage(xo, 128, NB * KP2, KP2, KP3, W3, b3, Ws3, bs3,
              h, y, xo, dis, sp, score, src, dst, w, map, perm,
              cnt, rs, cur, elist, bsum, readb, false);
    final_k<<<NB, 128>>>(readb, Wl, bl, out);
}

// round 10
// speedup vs baseline: 1.7816x; 1.0718x over previous
#include <cuda_runtime.h>
#include <math.h>
#include <float.h>

#define NB   50
#define NPG  2000
#define EPG  12000
#define ETOT (NB*EPG)      // 600000
#define N0   (NB*NPG)      // 100000
#define NHID 128
#define KP1  1600
#define KP2  1280
#define KP3  1024
#define KBLK 16

// ---------------- device scratch (load-time allocation, allowed) -------------
__device__ float g_h[(size_t)N0 * NHID];        // GEMM output
__device__ float g_y[(size_t)N0 * NHID];        // post-GCN activations
__device__ float g_xo[(size_t)NB * KP1 * NHID]; // pooled x
__device__ float g_dis[N0];
__device__ float g_sp[N0];
__device__ float g_score[N0];
__device__ int   g_src[ETOT];
__device__ int   g_dst[ETOT];
__device__ float g_w[ETOT];
__device__ int   g_map[N0];
__device__ int   g_perm[NB * KP1];
__device__ float g_read[NB * 256];              // accumulated x1+x2+x3
// CSR scratch
__device__ int   g_cnt[N0];
__device__ int   g_rs[N0 + 1];
__device__ int   g_cur[N0];
__device__ int   g_elist[ETOT];
__device__ int   g_bsum[1025];

// ---------------- misc -------------------------------------------------------
__global__ void edge_init_k(const int* __restrict__ ei, int* src, int* dst, float* w, int E) {
    int e = blockIdx.x * blockDim.x + threadIdx.x;
    if (e < E) { src[e] = ei[e]; dst[e] = ei[E + e]; w[e] = 1.0f; }
}

__global__ void zero_f_k(float* p, int n) {
    int i = blockIdx.x * blockDim.x + threadIdx.x;
    if (i < n) p[i] = 0.0f;
}

__global__ void zero_i_k(int* p, int n) {
    int i = blockIdx.x * blockDim.x + threadIdx.x;
    if (i < n) p[i] = 0;
}

// ---------------- CSR build --------------------------------------------------
__global__ void count_k(const int* __restrict__ dst, const float* __restrict__ w,
                        int* __restrict__ cnt, int E) {
    int e = blockIdx.x * blockDim.x + threadIdx.x;
    if (e < E && w[e] != 0.0f) atomicAdd(&cnt[dst[e]], 1);
}

__global__ void scan1_k(const int* __restrict__ cnt, int* __restrict__ excl,
                        int* __restrict__ bsum, int N) {
    __shared__ int s[1024];
    int tid = threadIdx.x;
    int i = blockIdx.x * 1024 + tid;
    int v = (i < N) ? cnt[i] : 0;
    s[tid] = v;
    __syncthreads();
#pragma unroll
    for (int off = 1; off < 1024; off <<= 1) {
        int t = (tid >= off) ? s[tid - off] : 0;
        __syncthreads();
        s[tid] += t;
        __syncthreads();
    }
    if (i < N) excl[i] = s[tid] - v;
    if (tid == 1023) bsum[blockIdx.x] = s[1023];
}

__global__ void scan2_k(int* __restrict__ bsum, int nblk) {
    __shared__ int s[1024];
    int tid = threadIdx.x;
    int v = (tid < nblk) ? bsum[tid] : 0;
    s[tid] = v;
    __syncthreads();
#pragma unroll
    for (int off = 1; off < 1024; off <<= 1) {
        int t = (tid >= off) ? s[tid - off] : 0;
        __syncthreads();
        s[tid] += t;
        __syncthreads();
    }
    if (tid < nblk) bsum[tid] = s[tid] - v;
    if (tid == nblk - 1) bsum[nblk] = s[tid];
}

__global__ void scan3_k(const int* __restrict__ excl, const int* __restrict__ bsum,
                        const int* __restrict__ cnt, int* __restrict__ rs,
                        int* __restrict__ cur, float* __restrict__ dis,
                        int N, int nblk) {
    int i = blockIdx.x * blockDim.x + threadIdx.x;
    if (i < N) {
        int r = excl[i] + bsum[i >> 10];
        rs[i] = r;
        cur[i] = r;
        dis[i] = rsqrtf((float)(cnt[i] + 1));
    } else if (i == N) {
        rs[N] = bsum[nblk];
    }
}

__global__ void fill_k(const int* __restrict__ src, const int* __restrict__ dst,
                       const float* __restrict__ w, int* __restrict__ cur,
                       int* __restrict__ elist, int E) {
    int e = blockIdx.x * blockDim.x + threadIdx.x;
    if (e < E && w[e] != 0.0f) {
        int pos = atomicAdd(&cur[dst[e]], 1);
        elist[pos] = src[e];
    }
}

// ---------------- f32x2 helpers ----------------------------------------------
__device__ __forceinline__ void fma2(unsigned long long& d, unsigned long long a,
                                     unsigned long long b) {
    asm("fma.rn.f32x2 %0, %1, %2, %0;" : "+l"(d) : "l"(a), "l"(b));
}
__device__ __forceinline__ float f2lo(unsigned long long v) {
    return __uint_as_float((unsigned)(v & 0xffffffffu));
}
__device__ __forceinline__ float f2hi(unsigned long long v) {
    return __uint_as_float((unsigned)(v >> 32));
}

// ---------------- GEMM: H[N,128] = X[N,K] @ W[K,128] -------------------------
// 128x128 tile, 256 threads, 8x8/thread via FFMA2, double-buffered smem,
// one __syncthreads per 16-k slab. Thread owns cols [tx*4,+4) U [64+tx*4,+4).
__global__ __launch_bounds__(256, 1)
void gemm_k(const float* __restrict__ X, const float* __restrict__ W,
            float* __restrict__ H, int N, int K) {
    __shared__ float2 a2[2][KBLK][128];   // duplicated (a,a); [buf][kk][row]
    __shared__ float  ws[2][KBLK][128];   // [buf][kk][col]
    int tid = threadIdx.x;
    int tx = tid & 15;
    int ty = tid >> 4;
    int row0 = blockIdx.x * 128;
    int lr  = tid >> 1;        // X-load row 0..127
    int lcg = tid & 1;         // X-load col half of slab
    int wr  = tid >> 4;        // W-load row in slab 0..15
    int wc  = (tid & 15) * 8;  // W-load col

    unsigned long long acc[8][4];
#pragma unroll
    for (int i = 0; i < 8; i++)
#pragma unroll
        for (int c = 0; c < 4; c++) acc[i][c] = 0ULL;

    const float* xrow = X + (size_t)(row0 + lr) * K;
    bool xok = (row0 + lr) < N;

    // preload slab 0 into buffer 0
    float4 v0 = make_float4(0.f,0.f,0.f,0.f), v1 = v0;
    if (xok) {
        v0 = *(const float4*)(xrow + lcg * 8);
        v1 = *(const float4*)(xrow + lcg * 8 + 4);
    }
    float4 w0 = *(const float4*)(W + (size_t)wr * 128 + wc);
    float4 w1 = *(const float4*)(W + (size_t)wr * 128 + wc + 4);
    {
        float xv[8] = {v0.x, v0.y, v0.z, v0.w, v1.x, v1.y, v1.z, v1.w};
#pragma unroll
        for (int j = 0; j < 8; j++)
            a2[0][lcg * 8 + j][lr] = make_float2(xv[j], xv[j]);
        *(float4*)&ws[0][wr][wc]     = w0;
        *(float4*)&ws[0][wr][wc + 4] = w1;
    }
    __syncthreads();

    int nslab = K / KBLK;
    int cur = 0;
    for (int s = 0; s < nslab; s++) {
        int nxt = cur ^ 1;
        bool more = (s + 1) < nslab;
        if (more) {
            int kb = (s + 1) * KBLK;
            v0 = make_float4(0.f,0.f,0.f,0.f); v1 = v0;
            if (xok) {
                v0 = *(const float4*)(xrow + kb + lcg * 8);
                v1 = *(const float4*)(xrow + kb + lcg * 8 + 4);
            }
            w0 = *(const float4*)(W + (size_t)(kb + wr) * 128 + wc);
            w1 = *(const float4*)(W + (size_t)(kb + wr) * 128 + wc + 4);
        }
#pragma unroll
        for (int kk = 0; kk < KBLK; kk++) {
            unsigned long long ap[8];
#pragma unroll
            for (int i = 0; i < 8; i++)
                ap[i] = *(const unsigned long long*)&a2[cur][kk][ty * 8 + i];
            float4 wa = *(float4*)&ws[cur][kk][tx * 4];
            float4 wb = *(float4*)&ws[cur][kk][64 + tx * 4];
            unsigned long long wv0 = *(unsigned long long*)&wa.x;
            unsigned long long wv1 = *(unsigned long long*)&wa.z;
            unsigned long long wv2 = *(unsigned long long*)&wb.x;
            unsigned long long wv3 = *(unsigned long long*)&wb.z;
#pragma unroll
            for (int i = 0; i < 8; i++) {
                fma2(acc[i][0], ap[i], wv0);
                fma2(acc[i][1], ap[i], wv1);
                fma2(acc[i][2], ap[i], wv2);
                fma2(acc[i][3], ap[i], wv3);
            }
        }
        if (more) {
            float xv[8] = {v0.x, v0.y, v0.z, v0.w, v1.x, v1.y, v1.z, v1.w};
#pragma unroll
            for (int j = 0; j < 8; j++)
                a2[nxt][lcg * 8 + j][lr] = make_float2(xv[j], xv[j]);
            *(float4*)&ws[nxt][wr][wc]     = w0;
            *(float4*)&ws[nxt][wr][wc + 4] = w1;
        }
        __syncthreads();
        cur = nxt;
    }

#pragma unroll
    for (int i = 0; i < 8; i++) {
        int grow = row0 + ty * 8 + i;
        if (grow < N) {
            float4 o0, o1;
            o0.x = f2lo(acc[i][0]); o0.y = f2hi(acc[i][0]);
            o0.z = f2lo(acc[i][1]); o0.w = f2hi(acc[i][1]);
            o1.x = f2lo(acc[i][2]); o1.y = f2hi(acc[i][2]);
            o1.z = f2lo(acc[i][3]); o1.w = f2hi(acc[i][3]);
            float* hp = H + (size_t)grow * 128;
            *(float4*)(hp + tx * 4)      = o0;
            *(float4*)(hp + 64 + tx * 4) = o1;
        }
    }
}

// ---------------- fused CSR aggregation + self-loop + bias + relu + score dot
__global__ void agg_fused_k(const int* __restrict__ rs, const int* __restrict__ elist,
                            const float* __restrict__ dis, const float* __restrict__ h,
                            const float* __restrict__ b, const float* __restrict__ Ws,
                            float* __restrict__ y, float* __restrict__ sp, int N) {
    int i = blockIdx.x * 8 + (threadIdx.x >> 5);
    int lane = threadIdx.x & 31;
    if (i >= N) return;
    int e0 = rs[i], e1 = rs[i + 1];
    float4 acc = make_float4(0.f, 0.f, 0.f, 0.f);
    for (int e = e0; e < e1; e++) {
        int s = elist[e];
        float ns = dis[s];
        float4 v = ((const float4*)(h + (size_t)s * 128))[lane];
        acc.x += v.x * ns; acc.y += v.y * ns;
        acc.z += v.z * ns; acc.w += v.w * ns;
    }
    float di = dis[i];
    float invdeg = 1.0f / (float)(e1 - e0 + 1);
    float4 hv = ((const float4*)(h + (size_t)i * 128))[lane];
    float4 bv = ((const float4*)b)[lane];
    float4 yv;
    yv.x = fmaxf(acc.x * di + hv.x * invdeg + bv.x, 0.f);
    yv.y = fmaxf(acc.y * di + hv.y * invdeg + bv.y, 0.f);
    yv.z = fmaxf(acc.z * di + hv.z * invdeg + bv.z, 0.f);
    yv.w = fmaxf(acc.w * di + hv.w * invdeg + bv.w, 0.f);
    ((float4*)(y + (size_t)i * 128))[lane] = yv;
    float4 wv = ((const float4*)Ws)[lane];
    float s = yv.x * wv.x + yv.y * wv.y + yv.z * wv.z + yv.w * wv.w;
#pragma unroll
    for (int off = 16; off > 0; off >>= 1) s += __shfl_down_sync(0xffffffffu, s, off);
    if (lane == 0) sp[i] = s;
}

// score[i] = (sum_in sp[src]*dis[src])*dis[i] + sp[i]/deg[i] + bs
__global__ void score_csr_k(const int* __restrict__ rs, const int* __restrict__ elist,
                            const float* __restrict__ dis, const float* __restrict__ sp,
                            const float* __restrict__ bs, float* __restrict__ score, int N) {
    int i = blockIdx.x * blockDim.x + threadIdx.x;
    if (i >= N) return;
    int e0 = rs[i], e1 = rs[i + 1];
    float acc = 0.0f;
    for (int e = e0; e < e1; e++) {
        int s = elist[e];
        acc += sp[s] * dis[s];
    }
    float invdeg = 1.0f / (float)(e1 - e0 + 1);
    score[i] = acc * dis[i] + sp[i] * invdeg + bs[0];
}

// ---------------- top-k per graph (bitonic sort of 2048 packed keys) --------
__global__ void topk_k(const float* __restrict__ score, int* __restrict__ map,
                       int* __restrict__ perm, int n, int k) {
    __shared__ unsigned long long keys[2048];
    int g = blockIdx.x;
    unsigned t = threadIdx.x;  // 1024 threads
    for (int p = t; p < 2048; p += 1024) {
        unsigned long long key;
        if (p < n) {
            unsigned u = __float_as_uint(score[g * n + p]);
            u = (u & 0x80000000u) ? ~u : (u | 0x80000000u);
            key = ((unsigned long long)(~u) << 32) | (unsigned)p;
        } else {
            key = ~0ULL;
        }
        keys[p] = key;
    }
    __syncthreads();
    for (unsigned size = 2; size < 2048; size <<= 1) {
        unsigned ddd = (t & (size >> 1)) != 0;
        for (unsigned stride = size >> 1; stride > 0; stride >>= 1) {
            __syncthreads();
            unsigned pos = 2 * t - (t & (stride - 1));
            unsigned long long a = keys[pos], bbv = keys[pos + stride];
            if ((a > bbv) != ddd) { keys[pos] = bbv; keys[pos + stride] = a; }
        }
    }
    for (unsigned stride = 1024; stride > 0; stride >>= 1) {
        __syncthreads();
        unsigned pos = 2 * t - (t & (stride - 1));
        unsigned long long a = keys[pos], bbv = keys[pos + stride];
        if (a > bbv) { keys[pos] = bbv; keys[pos + stride] = a; }
    }
    __syncthreads();
    for (int p = t; p < 2048; p += 1024) {
        unsigned idxv = (unsigned)(keys[p] & 0xFFFFFFFFu);
        if (idxv < (unsigned)n) {
            if (p < k) {
                map[g * n + (int)idxv] = g * k + p;
                perm[g * k + p] = g * n + (int)idxv;
            } else {
                map[g * n + (int)idxv] = -1;
            }
        }
    }
}

// gather + tanh gate fused
__global__ void gather_k(const float* __restrict__ y, const int* __restrict__ perm,
                         const float* __restrict__ score, float* __restrict__ xo, int Nout) {
    int idx = blockIdx.x * blockDim.x + threadIdx.x;
    if (idx < Nout * 32) {
        int m = idx >> 5;
        int q = idx & 31;
        int pm = perm[m];
        float tv = tanhf(score[pm]);
        float4 v = ((const float4*)(y + (size_t)pm * 128))[q];
        v.x *= tv; v.y *= tv; v.z *= tv; v.w *= tv;
        ((float4*)xo)[idx] = v;
    }
}

// readout: accumulate [max || mean] per graph into readb (+=)
__global__ void readout_k(const float* __restrict__ xo, int k, float* __restrict__ readb) {
    __shared__ float smx[8][128];
    __shared__ float ssm[8][128];
    int g = blockIdx.x;
    int f = threadIdx.x & 127;
    int ty = threadIdx.x >> 7;  // 0..7
    float mx = -FLT_MAX, sm = 0.0f;
    for (int i = ty; i < k; i += 8) {
        float v = xo[((size_t)(g * k + i)) * 128 + f];
        mx = fmaxf(mx, v);
        sm += v;
    }
    smx[ty][f] = mx;
    ssm[ty][f] = sm;
    __syncthreads();
    if (ty == 0) {
#pragma unroll
        for (int j = 1; j < 8; j++) { mx = fmaxf(mx, smx[j][f]); sm += ssm[j][f]; }
        readb[g * 256 + f]       += mx;
        readb[g * 256 + 128 + f] += sm / (float)k;
    }
}

__global__ void remap_k(const int* __restrict__ map, int* src, int* dst, float* w, int E) {
    int e = blockIdx.x * blockDim.x + threadIdx.x;
    if (e < E) {
        float ww = w[e];
        int ns = map[src[e]];
        int nd = map[dst[e]];
        bool valid = (ns >= 0) && (nd >= 0) && (ww > 0.0f);
        src[e] = valid ? ns : 0;
        dst[e] = valid ? nd : 0;
        w[e]   = valid ? ww : 0.0f;
    }
}

// out[g,j] = relu(sum_c readb[g,c]*Wl[c,j] + bl[j])
__global__ void final_k(const float* __restrict__ readb, const float* __restrict__ Wl,
                        const float* __restrict__ bl, float* __restrict__ out) {
    __shared__ float row[256];
    int g = blockIdx.x, j = threadIdx.x;  // 128 threads
    row[j]       = readb[g * 256 + j];
    row[128 + j] = readb[g * 256 + 128 + j];
    __syncthreads();
    float acc = bl[j];
#pragma unroll 8
    for (int c = 0; c < 256; c++) acc += row[c] * Wl[c * 128 + j];
    out[g * 128 + j] = fmaxf(acc, 0.0f);
}

// ---------------- host driver -----------------------------------------------
static void run_stage(const float* x_in, int Fin, int N, int n, int k,
                      const float* W, const float* b, const float* Ws, const float* bs,
                      float* h, float* y, float* xo,
                      float* dis, float* sp, float* score,
                      int* src, int* dst, float* w, int* map, int* perm,
                      int* cnt, int* rs, int* cur, int* elist, int* bsum,
                      float* readb, bool do_remap) {
    int Nout = NB * k;
    int nblk = (N + 1023) / 1024;
    // CSR build
    zero_i_k<<<(N + 255) / 256, 256>>>(cnt, N);
    count_k<<<(ETOT + 255) / 256, 256>>>(dst, w, cnt, ETOT);
    scan1_k<<<nblk, 1024>>>(cnt, cur /*excl scratch*/, bsum, N);
    scan2_k<<<1, 1024>>>(bsum, nblk);
    scan3_k<<<(N + 256) / 256, 256>>>(cur, bsum, cnt, rs, cnt /*reuse cnt as cursor*/, dis, N, nblk);
    fill_k<<<(ETOT + 255) / 256, 256>>>(src, dst, w, cnt, elist, ETOT);
    // dense
    gemm_k<<<(N + 127) / 128, 256>>>(x_in, W, h, N, Fin);
    agg_fused_k<<<(N + 7) / 8, 256>>>(rs, elist, dis, h, b, Ws, y, sp, N);
    score_csr_k<<<(N + 255) / 256, 256>>>(rs, elist, dis, sp, bs, score, N);
    topk_k<<<NB, 1024>>>(score, map, perm, n, k);
    gather_k<<<(Nout * 32 + 255) / 256, 256>>>(y, perm, score, xo, Nout);
    readout_k<<<NB, 1024>>>(xo, k, readb);
    if (do_remap)
        remap_k<<<(ETOT + 255) / 256, 256>>>(map, src, dst, w, ETOT);
}

extern "C" void kernel_launch(void* const* d_in, const int* in_sizes, int n_in,
                              void* d_out, int out_size) {
    const float* x   = (const float*)d_in[0];
    const float* W1  = (const float*)d_in[1];
    const float* b1  = (const float*)d_in[2];
    const float* Ws1 = (const float*)d_in[3];
    const float* bs1 = (const float*)d_in[4];
    const float* W2  = (const float*)d_in[5];
    const float* b2  = (const float*)d_in[6];
    const float* Ws2 = (const float*)d_in[7];
    const float* bs2 = (const float*)d_in[8];
    const float* W3  = (const float*)d_in[9];
    const float* b3  = (const float*)d_in[10];
    const float* Ws3 = (const float*)d_in[11];
    const float* bs3 = (const float*)d_in[12];
    const float* Wl  = (const float*)d_in[13];
    const float* bl  = (const float*)d_in[14];
    const int*   ei  = (const int*)d_in[15];
    float* out = (float*)d_out;

    float *h, *y, *xo, *dis, *sp, *score, *w, *readb;
    int *src, *dst, *map, *perm, *cnt, *rs, *cur, *elist, *bsum;
    cudaGetSymbolAddress((void**)&h, g_h);
    cudaGetSymbolAddress((void**)&y, g_y);
    cudaGetSymbolAddress((void**)&xo, g_xo);
    cudaGetSymbolAddress((void**)&dis, g_dis);
    cudaGetSymbolAddress((void**)&sp, g_sp);
    cudaGetSymbolAddress((void**)&score, g_score);
    cudaGetSymbolAddress((void**)&src, g_src);
    cudaGetSymbolAddress((void**)&dst, g_dst);
    cudaGetSymbolAddress((void**)&w, g_w);
    cudaGetSymbolAddress((void**)&map, g_map);
    cudaGetSymbolAddress((void**)&perm, g_perm);
    cudaGetSymbolAddress((void**)&readb, g_read);
    cudaGetSymbolAddress((void**)&cnt, g_cnt);
    cudaGetSymbolAddress((void**)&rs, g_rs);
    cudaGetSymbolAddress((void**)&cur, g_cur);
    cudaGetSymbolAddress((void**)&elist, g_elist);
    cudaGetSymbolAddress((void**)&bsum, g_bsum);

    edge_init_k<<<(ETOT + 255) / 256, 256>>>(ei, src, dst, w, ETOT);
    zero_f_k<<<(NB * 256 + 255) / 256, 256>>>(readb, NB * 256);

    run_stage(x, 256, N0, NPG, KP1, W1, b1, Ws1, bs1,
              h, y, xo, dis, sp, score, src, dst, w, map, perm,
              cnt, rs, cur, elist, bsum, readb, true);
    run_stage(xo, 128, NB * KP1, KP1, KP2, W2, b2, Ws2, bs2,
              h, y, xo, dis, sp, score, src, dst, w, map, perm,
              cnt, rs, cur, elist, bsum, readb, true);
    run_stage(xo, 128, NB * KP2, KP2, KP3, W3, b3, Ws3, bs3,
              h, y, xo, dis, sp, score, src, dst, w, map, perm,
              cnt, rs, cur, elist, bsum, readb, false);
    final_k<<<NB, 128>>>(readb, Wl, bl, out);
}

// round 12
// speedup vs baseline: 1.8753x; 1.0526x over previous
#include <cuda_runtime.h>
#include <math.h>
#include <float.h>

#define NB   50
#define NPG  2000
#define EPG  12000
#define ETOT (NB*EPG)      // 600000
#define N0   (NB*NPG)      // 100000
#define NHID 128
#define KP1  1600
#define KP2  1280
#define KP3  1024
#define KBLK 16

// ---------------- device scratch (load-time allocation, allowed) -------------
__device__ float g_h[(size_t)N0 * NHID];        // GEMM output
__device__ float g_y[(size_t)N0 * NHID];        // post-GCN activations
__device__ float g_xo[(size_t)NB * KP1 * NHID]; // pooled x
__device__ float g_dis[N0];
__device__ float g_sp[N0];
__device__ float g_score[N0];
__device__ int   g_src[ETOT];
__device__ int   g_dst[ETOT];
__device__ float g_w[ETOT];
__device__ int   g_map[N0];
__device__ int   g_perm[NB * KP1];
__device__ float g_read[NB * 256];              // accumulated x1+x2+x3
// CSR scratch
__device__ int   g_cnt[N0];
__device__ int   g_rs[N0 + 1];
__device__ int   g_cur[N0];
__device__ int   g_elist[ETOT];
__device__ int   g_bsum[1025];

// ---------------- misc -------------------------------------------------------
// edge init + degree histogram fused (cnt must be zeroed before)
__global__ void edge_init_k(const int* __restrict__ ei, int* src, int* dst, float* w,
                            int* __restrict__ cnt, int E) {
    int e = blockIdx.x * blockDim.x + threadIdx.x;
    if (e < E) {
        int s = ei[e], d = ei[E + e];
        src[e] = s; dst[e] = d; w[e] = 1.0f;
        atomicAdd(&cnt[d], 1);
    }
}

__global__ void zero_f_k(float* p, int n) {
    int i = blockIdx.x * blockDim.x + threadIdx.x;
    if (i < n) p[i] = 0.0f;
}

__global__ void zero_i_k(int* p, int n) {
    int i = blockIdx.x * blockDim.x + threadIdx.x;
    if (i < n) p[i] = 0;
}

// ---------------- CSR scan ---------------------------------------------------
__global__ void scan1_k(const int* __restrict__ cnt, int* __restrict__ excl,
                        int* __restrict__ bsum, int N) {
    __shared__ int s[1024];
    int tid = threadIdx.x;
    int i = blockIdx.x * 1024 + tid;
    int v = (i < N) ? cnt[i] : 0;
    s[tid] = v;
    __syncthreads();
#pragma unroll
    for (int off = 1; off < 1024; off <<= 1) {
        int t = (tid >= off) ? s[tid - off] : 0;
        __syncthreads();
        s[tid] += t;
        __syncthreads();
    }
    if (i < N) excl[i] = s[tid] - v;
    if (tid == 1023) bsum[blockIdx.x] = s[1023];
}

__global__ void scan2_k(int* __restrict__ bsum, int nblk) {
    __shared__ int s[1024];
    int tid = threadIdx.x;
    int v = (tid < nblk) ? bsum[tid] : 0;
    s[tid] = v;
    __syncthreads();
#pragma unroll
    for (int off = 1; off < 1024; off <<= 1) {
        int t = (tid >= off) ? s[tid - off] : 0;
        __syncthreads();
        s[tid] += t;
        __syncthreads();
    }
    if (tid < nblk) bsum[tid] = s[tid] - v;
    if (tid == nblk - 1) bsum[nblk] = s[tid];
}

__global__ void scan3_k(const int* __restrict__ excl, const int* __restrict__ bsum,
                        const int* __restrict__ cnt, int* __restrict__ rs,
                        int* __restrict__ cur, float* __restrict__ dis,
                        int N, int nblk) {
    int i = blockIdx.x * blockDim.x + threadIdx.x;
    if (i < N) {
        int r = excl[i] + bsum[i >> 10];
        rs[i] = r;
        cur[i] = r;
        dis[i] = rsqrtf((float)(cnt[i] + 1));
    } else if (i == N) {
        rs[N] = bsum[nblk];
    }
}

__global__ void fill_k(const int* __restrict__ src, const int* __restrict__ dst,
                       const float* __restrict__ w, int* __restrict__ cur,
                       int* __restrict__ elist, int E) {
    int e = blockIdx.x * blockDim.x + threadIdx.x;
    if (e < E && w[e] != 0.0f) {
        int pos = atomicAdd(&cur[dst[e]], 1);
        elist[pos] = src[e];
    }
}

// ---------------- f32x2 helpers ----------------------------------------------
__device__ __forceinline__ void fma2(unsigned long long& d, unsigned long long a,
                                     unsigned long long b) {
    asm("fma.rn.f32x2 %0, %1, %2, %0;" : "+l"(d) : "l"(a), "l"(b));
}
__device__ __forceinline__ float f2lo(unsigned long long v) {
    return __uint_as_float((unsigned)(v & 0xffffffffu));
}
__device__ __forceinline__ float f2hi(unsigned long long v) {
    return __uint_as_float((unsigned)(v >> 32));
}

// ---------------- GEMM: H[N,128] = X[N,K] @ W[K,128] -------------------------
// 128x128 tile, 256 threads, 8x8/thread via FFMA2, double-buffered smem.
__global__ __launch_bounds__(256, 1)
void gemm_k(const float* __restrict__ X, const float* __restrict__ W,
            float* __restrict__ H, int N, int K) {
    __shared__ float2 a2[2][KBLK][128];   // duplicated (a,a); [buf][kk][row]
    __shared__ float  ws[2][KBLK][128];   // [buf][kk][col]
    int tid = threadIdx.x;
    int tx = tid & 15;
    int ty = tid >> 4;
    int row0 = blockIdx.x * 128;
    int lr  = tid >> 1;        // X-load row 0..127
    int lcg = tid & 1;         // X-load col half of slab
    int wr  = tid >> 4;        // W-load row in slab 0..15
    int wc  = (tid & 15) * 8;  // W-load col

    unsigned long long acc[8][4];
#pragma unroll
    for (int i = 0; i < 8; i++)
#pragma unroll
        for (int c = 0; c < 4; c++) acc[i][c] = 0ULL;

    const float* xrow = X + (size_t)(row0 + lr) * K;
    bool xok = (row0 + lr) < N;

    float4 v0 = make_float4(0.f,0.f,0.f,0.f), v1 = v0;
    if (xok) {
        v0 = *(const float4*)(xrow + lcg * 8);
        v1 = *(const float4*)(xrow + lcg * 8 + 4);
    }
    float4 w0 = *(const float4*)(W + (size_t)wr * 128 + wc);
    float4 w1 = *(const float4*)(W + (size_t)wr * 128 + wc + 4);
    {
        float xv[8] = {v0.x, v0.y, v0.z, v0.w, v1.x, v1.y, v1.z, v1.w};
#pragma unroll
        for (int j = 0; j < 8; j++)
            a2[0][lcg * 8 + j][lr] = make_float2(xv[j], xv[j]);
        *(float4*)&ws[0][wr][wc]     = w0;
        *(float4*)&ws[0][wr][wc + 4] = w1;
    }
    __syncthreads();

    int nslab = K / KBLK;
    int cur = 0;
    for (int s = 0; s < nslab; s++) {
        int nxt = cur ^ 1;
        bool more = (s + 1) < nslab;
        if (more) {
            int kb = (s + 1) * KBLK;
            v0 = make_float4(0.f,0.f,0.f,0.f); v1 = v0;
            if (xok) {
                v0 = *(const float4*)(xrow + kb + lcg * 8);
                v1 = *(const float4*)(xrow + kb + lcg * 8 + 4);
            }
            w0 = *(const float4*)(W + (size_t)(kb + wr) * 128 + wc);
            w1 = *(const float4*)(W + (size_t)(kb + wr) * 128 + wc + 4);
        }
#pragma unroll
        for (int kk = 0; kk < KBLK; kk++) {
            unsigned long long ap[8];
#pragma unroll
            for (int i = 0; i < 8; i++)
                ap[i] = *(const unsigned long long*)&a2[cur][kk][ty * 8 + i];
            float4 wa = *(float4*)&ws[cur][kk][tx * 4];
            float4 wb = *(float4*)&ws[cur][kk][64 + tx * 4];
            unsigned long long wv0 = *(unsigned long long*)&wa.x;
            unsigned long long wv1 = *(unsigned long long*)&wa.z;
            unsigned long long wv2 = *(unsigned long long*)&wb.x;
            unsigned long long wv3 = *(unsigned long long*)&wb.z;
#pragma unroll
            for (int i = 0; i < 8; i++) {
                fma2(acc[i][0], ap[i], wv0);
                fma2(acc[i][1], ap[i], wv1);
                fma2(acc[i][2], ap[i], wv2);
                fma2(acc[i][3], ap[i], wv3);
            }
        }
        if (more) {
            float xv[8] = {v0.x, v0.y, v0.z, v0.w, v1.x, v1.y, v1.z, v1.w};
#pragma unroll
            for (int j = 0; j < 8; j++)
                a2[nxt][lcg * 8 + j][lr] = make_float2(xv[j], xv[j]);
            *(float4*)&ws[nxt][wr][wc]     = w0;
            *(float4*)&ws[nxt][wr][wc + 4] = w1;
        }
        __syncthreads();
        cur = nxt;
    }

#pragma unroll
    for (int i = 0; i < 8; i++) {
        int grow = row0 + ty * 8 + i;
        if (grow < N) {
            float4 o0, o1;
            o0.x = f2lo(acc[i][0]); o0.y = f2hi(acc[i][0]);
            o0.z = f2lo(acc[i][1]); o0.w = f2hi(acc[i][1]);
            o1.x = f2lo(acc[i][2]); o1.y = f2hi(acc[i][2]);
            o1.z = f2lo(acc[i][3]); o1.w = f2hi(acc[i][3]);
            float* hp = H + (size_t)grow * 128;
            *(float4*)(hp + tx * 4)      = o0;
            *(float4*)(hp + 64 + tx * 4) = o1;
        }
    }
}

// ---------------- fused CSR aggregation + self-loop + bias + relu + score dot
__global__ void agg_fused_k(const int* __restrict__ rs, const int* __restrict__ elist,
                            const float* __restrict__ dis, const float* __restrict__ h,
                            const float* __restrict__ b, const float* __restrict__ Ws,
                            float* __restrict__ y, float* __restrict__ sp, int N) {
    int i = blockIdx.x * 8 + (threadIdx.x >> 5);
    int lane = threadIdx.x & 31;
    if (i >= N) return;
    int e0 = rs[i], e1 = rs[i + 1];
    float4 acc = make_float4(0.f, 0.f, 0.f, 0.f);
    for (int e = e0; e < e1; e++) {
        int s = elist[e];
        float ns = dis[s];
        float4 v = ((const float4*)(h + (size_t)s * 128))[lane];
        acc.x += v.x * ns; acc.y += v.y * ns;
        acc.z += v.z * ns; acc.w += v.w * ns;
    }
    float di = dis[i];
    float invdeg = 1.0f / (float)(e1 - e0 + 1);
    float4 hv = ((const float4*)(h + (size_t)i * 128))[lane];
    float4 bv = ((const float4*)b)[lane];
    float4 yv;
    yv.x = fmaxf(acc.x * di + hv.x * invdeg + bv.x, 0.f);
    yv.y = fmaxf(acc.y * di + hv.y * invdeg + bv.y, 0.f);
    yv.z = fmaxf(acc.z * di + hv.z * invdeg + bv.z, 0.f);
    yv.w = fmaxf(acc.w * di + hv.w * invdeg + bv.w, 0.f);
    ((float4*)(y + (size_t)i * 128))[lane] = yv;
    float4 wv = ((const float4*)Ws)[lane];
    float s = yv.x * wv.x + yv.y * wv.y + yv.z * wv.z + yv.w * wv.w;
#pragma unroll
    for (int off = 16; off > 0; off >>= 1) s += __shfl_down_sync(0xffffffffu, s, off);
    if (lane == 0) sp[i] = s;
}

// score[i] = (sum_in sp[src]*dis[src])*dis[i] + sp[i]/deg[i] + bs
__global__ void score_csr_k(const int* __restrict__ rs, const int* __restrict__ elist,
                            const float* __restrict__ dis, const float* __restrict__ sp,
                            const float* __restrict__ bs, float* __restrict__ score, int N) {
    int i = blockIdx.x * blockDim.x + threadIdx.x;
    if (i >= N) return;
    int e0 = rs[i], e1 = rs[i + 1];
    float acc = 0.0f;
    for (int e = e0; e < e1; e++) {
        int s = elist[e];
        acc += sp[s] * dis[s];
    }
    float invdeg = 1.0f / (float)(e1 - e0 + 1);
    score[i] = acc * dis[i] + sp[i] * invdeg + bs[0];
}

// ---------------- top-k per graph (bitonic sort of 2048 packed keys) --------
__global__ void topk_k(const float* __restrict__ score, int* __restrict__ map,
                       int* __restrict__ perm, int n, int k) {
    __shared__ unsigned long long keys[2048];
    int g = blockIdx.x;
    unsigned t = threadIdx.x;  // 1024 threads
    for (int p = t; p < 2048; p += 1024) {
        unsigned long long key;
        if (p < n) {
            unsigned u = __float_as_uint(score[g * n + p]);
            u = (u & 0x80000000u) ? ~u : (u | 0x80000000u);
            key = ((unsigned long long)(~u) << 32) | (unsigned)p;
        } else {
            key = ~0ULL;
        }
        keys[p] = key;
    }
    __syncthreads();
    for (unsigned size = 2; size < 2048; size <<= 1) {
        unsigned ddd = (t & (size >> 1)) != 0;
        for (unsigned stride = size >> 1; stride > 0; stride >>= 1) {
            __syncthreads();
            unsigned pos = 2 * t - (t & (stride - 1));
            unsigned long long a = keys[pos], bbv = keys[pos + stride];
            if ((a > bbv) != ddd) { keys[pos] = bbv; keys[pos + stride] = a; }
        }
    }
    for (unsigned stride = 1024; stride > 0; stride >>= 1) {
        __syncthreads();
        unsigned pos = 2 * t - (t & (stride - 1));
        unsigned long long a = keys[pos], bbv = keys[pos + stride];
        if (a > bbv) { keys[pos] = bbv; keys[pos + stride] = a; }
    }
    __syncthreads();
    for (int p = t; p < 2048; p += 1024) {
        unsigned idxv = (unsigned)(keys[p] & 0xFFFFFFFFu);
        if (idxv < (unsigned)n) {
            if (p < k) {
                map[g * n + (int)idxv] = g * k + p;
                perm[g * k + p] = g * n + (int)idxv;
            } else {
                map[g * n + (int)idxv] = -1;
            }
        }
    }
}

// gather + tanh gate fused; also zeroes cnt for the next stage's histogram
__global__ void gather_k(const float* __restrict__ y, const int* __restrict__ perm,
                         const float* __restrict__ score, float* __restrict__ xo,
                         int* __restrict__ cnt, int Nout) {
    int idx = blockIdx.x * blockDim.x + threadIdx.x;
    if (idx < Nout) cnt[idx] = 0;
    if (idx < Nout * 32) {
        int m = idx >> 5;
        int q = idx & 31;
        int pm = perm[m];
        float tv = tanhf(score[pm]);
        float4 v = ((const float4*)(y + (size_t)pm * 128))[q];
        v.x *= tv; v.y *= tv; v.z *= tv; v.w *= tv;
        ((float4*)xo)[idx] = v;
    }
}

// readout: accumulate [max || mean] per graph into readb (+=)
__global__ void readout_k(const float* __restrict__ xo, int k, float* __restrict__ readb) {
    __shared__ float smx[8][128];
    __shared__ float ssm[8][128];
    int g = blockIdx.x;
    int f = threadIdx.x & 127;
    int ty = threadIdx.x >> 7;  // 0..7
    float mx = -FLT_MAX, sm = 0.0f;
    for (int i = ty; i < k; i += 8) {
        float v = xo[((size_t)(g * k + i)) * 128 + f];
        mx = fmaxf(mx, v);
        sm += v;
    }
    smx[ty][f] = mx;
    ssm[ty][f] = sm;
    __syncthreads();
    if (ty == 0) {
#pragma unroll
        for (int j = 1; j < 8; j++) { mx = fmaxf(mx, smx[j][f]); sm += ssm[j][f]; }
        readb[g * 256 + f]       += mx;
        readb[g * 256 + 128 + f] += sm / (float)k;
    }
}

// remap + next-stage degree histogram fused (cnt zeroed by gather_k)
__global__ void remap_k(const int* __restrict__ map, int* src, int* dst, float* w,
                        int* __restrict__ cnt, int E) {
    int e = blockIdx.x * blockDim.x + threadIdx.x;
    if (e < E) {
        float ww = w[e];
        int ns = map[src[e]];
        int nd = map[dst[e]];
        bool valid = (ns >= 0) && (nd >= 0) && (ww > 0.0f);
        src[e] = valid ? ns : 0;
        dst[e] = valid ? nd : 0;
        w[e]   = valid ? ww : 0.0f;
        if (valid) atomicAdd(&cnt[nd], 1);
    }
}

// out[g,j] = relu(sum_c readb[g,c]*Wl[c,j] + bl[j])
__global__ void final_k(const float* __restrict__ readb, const float* __restrict__ Wl,
                        const float* __restrict__ bl, float* __restrict__ out) {
    __shared__ float row[256];
    int g = blockIdx.x, j = threadIdx.x;  // 128 threads
    row[j]       = readb[g * 256 + j];
    row[128 + j] = readb[g * 256 + 128 + j];
    __syncthreads();
    float acc = bl[j];
#pragma unroll 8
    for (int c = 0; c < 256; c++) acc += row[c] * Wl[c * 128 + j];
    out[g * 128 + j] = fmaxf(acc, 0.0f);
}

// ---------------- host driver -----------------------------------------------
// cnt must already hold the in-degree histogram for this stage on entry.
static void run_stage(const float* x_in, int Fin, int N, int n, int k,
                      const float* W, const float* b, const float* Ws, const float* bs,
                      float* h, float* y, float* xo,
                      float* dis, float* sp, float* score,
                      int* src, int* dst, float* w, int* map, int* perm,
                      int* cnt, int* rs, int* cur, int* elist, int* bsum,
                      float* readb, bool do_remap) {
    int Nout = NB * k;
    int nblk = (N + 1023) / 1024;
    scan1_k<<<nblk, 1024>>>(cnt, cur /*excl scratch*/, bsum, N);
    scan2_k<<<1, 1024>>>(bsum, nblk);
    gemm_k<<<(N + 127) / 128, 256>>>(x_in, W, h, N, Fin);   // independent of CSR
    scan3_k<<<(N + 256) / 256, 256>>>(cur, bsum, cnt, rs, cnt /*cursor*/, dis, N, nblk);
    fill_k<<<(ETOT + 255) / 256, 256>>>(src, dst, w, cnt, elist, ETOT);
    agg_fused_k<<<(N + 7) / 8, 256>>>(rs, elist, dis, h, b, Ws, y, sp, N);
    score_csr_k<<<(N + 255) / 256, 256>>>(rs, elist, dis, sp, bs, score, N);
    topk_k<<<NB, 1024>>>(score, map, perm, n, k);
    gather_k<<<(Nout * 32 + 255) / 256, 256>>>(y, perm, score, xo, cnt, Nout);
    readout_k<<<NB, 1024>>>(xo, k, readb);
    if (do_remap)
        remap_k<<<(ETOT + 255) / 256, 256>>>(map, src, dst, w, cnt, ETOT);
}

extern "C" void kernel_launch(void* const* d_in, const int* in_sizes, int n_in,
                              void* d_out, int out_size) {
    const float* x   = (const float*)d_in[0];
    const float* W1  = (const float*)d_in[1];
    const float* b1  = (const float*)d_in[2];
    const float* Ws1 = (const float*)d_in[3];
    const float* bs1 = (const float*)d_in[4];
    const float* W2  = (const float*)d_in[5];
    const float* b2  = (const float*)d_in[6];
    const float* Ws2 = (const float*)d_in[7];
    const float* bs2 = (const float*)d_in[8];
    const float* W3  = (const float*)d_in[9];
    const float* b3  = (const float*)d_in[10];
    const float* Ws3 = (const float*)d_in[11];
    const float* bs3 = (const float*)d_in[12];
    const float* Wl  = (const float*)d_in[13];
    const float* bl  = (const float*)d_in[14];
    const int*   ei  = (const int*)d_in[15];
    float* out = (float*)d_out;

    float *h, *y, *xo, *dis, *sp, *score, *w, *readb;
    int *src, *dst, *map, *perm, *cnt, *rs, *cur, *elist, *bsum;
    cudaGetSymbolAddress((void**)&h, g_h);
    cudaGetSymbolAddress((void**)&y, g_y);
    cudaGetSymbolAddress((void**)&xo, g_xo);
    cudaGetSymbolAddress((void**)&dis, g_dis);
    cudaGetSymbolAddress((void**)&sp, g_sp);
    cudaGetSymbolAddress((void**)&score, g_score);
    cudaGetSymbolAddress((void**)&src, g_src);
    cudaGetSymbolAddress((void**)&dst, g_dst);
    cudaGetSymbolAddress((void**)&w, g_w);
    cudaGetSymbolAddress((void**)&map, g_map);
    cudaGetSymbolAddress((void**)&perm, g_perm);
    cudaGetSymbolAddress((void**)&readb, g_read);
    cudaGetSymbolAddress((void**)&cnt, g_cnt);
    cudaGetSymbolAddress((void**)&rs, g_rs);
    cudaGetSymbolAddress((void**)&cur, g_cur);
    cudaGetSymbolAddress((void**)&elist, g_elist);
    cudaGetSymbolAddress((void**)&bsum, g_bsum);

    // launch order puts stage-1 gemm_k at global launch #6 (ncu -s 5 -c 1)
    zero_i_k<<<(N0 + 255) / 256, 256>>>(cnt, N0);                 // 1
    zero_f_k<<<(NB * 256 + 255) / 256, 256>>>(readb, NB * 256);   // 2
    edge_init_k<<<(ETOT + 255) / 256, 256>>>(ei, src, dst, w, cnt, ETOT); // 3

    run_stage(x, 256, N0, NPG, KP1, W1, b1, Ws1, bs1,             // 4,5,6(gemm),...
              h, y, xo, dis, sp, score, src, dst, w, map, perm,
              cnt, rs, cur, elist, bsum, readb, true);
    run_stage(xo, 128, NB * KP1, KP1, KP2, W2, b2, Ws2, bs2,
              h, y, xo, dis, sp, score, src, dst, w, map, perm,
              cnt, rs, cur, elist, bsum, readb, true);
    run_stage(xo, 128, NB * KP2, KP2, KP3, W3, b3, Ws3, bs3,
              h, y, xo, dis, sp, score, src, dst, w, map, perm,
              cnt, rs, cur, elist, bsum, readb, false);
    final_k<<<NB, 128>>>(readb, Wl, bl, out);
}